// round 8
// baseline (speedup 1.0000x reference)
#include <cuda_runtime.h>
#include <math.h>

#define N 32
#define LDT 33                 // padded tile leading dim
#define WARPS_PER_CTA 4
#define NTHREADS (WARPS_PER_CTA * 32)
#define NSWEEP 6
#define MINSWEEP 3
#define JTOL 1e-3f
#define EPS 1e-6f
#define NB_BANDS 9
#define T_DIM 128
#define B_DIM 8

// Jacobi rotation for implicit 2x2 [[np, bpq],[bpq, nq]]. MUFU-fast, clamped.
__device__ __forceinline__ void fastrot(float np, float nq, float bpq,
                                        float& c, float& s)
{
    if (fabsf(bpq) > 1e-20f) {
        float tau = __fdividef(nq - np, 2.0f * bpq);
        tau = fminf(fmaxf(tau, -1e15f), 1e15f);
        float t2  = fmaf(tau, tau, 1.0f);
        float den = fabsf(tau) + t2 * rsqrtf(t2);      // |tau| + sqrt(1+tau^2)
        float tt  = __fdividef(1.0f, den);
        tt = (tau >= 0.0f) ? tt : -tt;
        c = rsqrtf(fmaf(tt, tt, 1.0f));
        s = tt * c;
    } else { c = 1.0f; s = 0.0f; }
}

// Warp-cooperative in-place Cholesky (lower) of SPD 32x32 in smem. lane = row.
// Leaves junk in the strict upper triangle.
__device__ __forceinline__ void warp_chol(float* S, int lane)
{
    for (int k = 0; k < N; ++k) {
        float akk = S[k * LDT + k];                    // all lanes read
        float inv = rsqrtf(fmaxf(akk, 1e-12f));
        __syncwarp();
        float lik = 0.0f;
        if (lane >= k) {
            float v = S[lane * LDT + k];
            lik = (lane == k) ? akk * inv : v * inv;
            S[lane * LDT + k] = lik;
        }
        __syncwarp();
        if (lane > k) {
            for (int j = k + 1; j <= lane; ++j)        // S[j,k] broadcast reads
                S[lane * LDT + j] -= lik * S[j * LDT + k];
        }
        __syncwarp();
    }
}

// ---------------------------------------------------------------------------
// One WARP per output site:
//   L = chol(A); Lb = chol(B); G = L^{-1} Lb  (lane = column, registers)
//   one-sided Jacobi on G's columns (XOR ordering, shfl_xor exchange,
//   per-warp early exit) -> eigensystem of C = G G^T
//   mean = Z Z^T with z_c = L g_c * lambda_c^{(w2-1)/2}
// Requires K == 2 (KERNEL_SIZE of this problem).
// ---------------------------------------------------------------------------
__global__ void __launch_bounds__(NTHREADS, 6)
wfm_kernel(const float* __restrict__ x, const float* __restrict__ rw,
           float* __restrict__ out, int t_out)
{
    __shared__ float tiles[WARPS_PER_CTA][2][N * LDT];

    const int lane = threadIdx.x & 31;
    const int wrp  = threadIdx.x >> 5;
    float* sA = tiles[wrp][0];                 // A -> L  (upper zeroed later)
    float* sB = tiles[wrp][1];                 // B -> Lb -> Z

    const int site = blockIdx.x * WARPS_PER_CTA + wrp;
    const int band = site % NB_BANDS;
    const int tmp  = site / NB_BANDS;
    const int tt   = tmp % t_out;
    const int b    = tmp / t_out;

    const float* Ma = x + ((size_t)(b * T_DIM + tt) * NB_BANDS + band) * (size_t)(N * N);
    const float* Mb = Ma + (size_t)NB_BANDS * N * N;

    // softmax weight w2 (K == 2), computed redundantly per thread
    float r0 = rw[0], r1 = rw[1];
    float mx = fmaxf(r0, r1);
    float e0 = __expf(r0 - mx), e1 = __expf(r1 - mx);
    const float w2 = e1 / (e0 + e1);

    // load A, B into per-warp tiles (coalesced)
#pragma unroll
    for (int t = 0; t < N; ++t) {
        sA[t * LDT + lane] = Ma[t * N + lane];
        sB[t * LDT + lane] = Mb[t * N + lane];
    }
    __syncwarp();

    warp_chol(sA, lane);                       // sA lower = L
    warp_chol(sB, lane);                       // sB lower = Lb

    // zero strict upper of sA (so Z = L*u can be unconditional later)
#pragma unroll
    for (int j = 0; j < N; ++j)
        if (j > lane) sA[lane * LDT + j] = 0.0f;
    __syncwarp();

    // G = L^{-1} Lb, lane = column c. Lower triangular: u[k] = 0 for k < c.
    float u[N];
#pragma unroll
    for (int k = 0; k < N; ++k) {
        float acc = sB[k * LDT + lane];        // Lb[k, c] (junk for k < c, masked)
#pragma unroll
        for (int j = 0; j < k; ++j)
            acc -= sA[k * LDT + j] * u[j];     // broadcast reads of L row k
        float val = acc * __fdividef(1.0f, sA[k * LDT + k]);
        u[k] = (k >= lane) ? val : 0.0f;
    }

    float nu = 0.0f;                           // ||u||^2, maintained exactly
#pragma unroll
    for (int i = 0; i < N; ++i) nu = fmaf(u[i], u[i], nu);

    // ---------------- one-sided Jacobi, XOR ordering ----------------
#pragma unroll 1
    for (int sweep = 0; sweep < NSWEEP; ++sweep) {
        bool bad = false;
#pragma unroll 1
        for (int m = 1; m < 32; ++m) {
            const int partner = lane ^ m;

            float pu[N];
#pragma unroll
            for (int i = 0; i < N; ++i)
                pu[i] = __shfl_xor_sync(0xffffffffu, u[i], m);

            float bu = 0.0f;
#pragma unroll
            for (int i = 0; i < N; ++i) bu = fmaf(u[i], pu[i], bu);  // pair-identical

            float pn  = __shfl_xor_sync(0xffffffffu, nu, m);
            bool  isp = lane < partner;

            // convergence residual (scale-free, pre-rotation)
            bad |= (fabsf(bu) * rsqrtf(nu * pn) > JTOL);

            float np = isp ? nu : pn;
            float nq = isp ? pn : nu;

            float c, s;
            fastrot(np, nq, bu, c, s);
            float ss = isp ? -s : s;

#pragma unroll
            for (int i = 0; i < N; ++i)
                u[i] = fmaf(ss, pu[i], c * u[i]);

            // exact norm rotation identity
            nu = c * c * nu + s * s * pn + 2.0f * ss * c * bu;
        }
        if (sweep >= MINSWEEP - 1 && !__any_sync(0xffffffffu, bad)) break;
    }

    // eigenvalue = exact final column norm; scale columns:
    // z_c = L * u_c * lambda^{(w2-1)/2}  -> mean = Z Z^T
    float lam = 0.0f;
#pragma unroll
    for (int i = 0; i < N; ++i) lam = fmaf(u[i], u[i], lam);
    lam = fmaxf(lam, EPS);
    float scale = __expf(0.5f * (w2 - 1.0f) * __logf(lam));
#pragma unroll
    for (int i = 0; i < N; ++i) u[i] *= scale;

    __syncwarp();
    // Z = L * u (store columns into sB, reuse tile)
    for (int i = 0; i < N; ++i) {
        float acc = 0.0f;
#pragma unroll
        for (int j = 0; j < N; ++j)
            acc = fmaf(sA[i * LDT + j], u[j], acc);   // upper of L is zeroed
        sB[i * LDT + lane] = acc;
    }
    __syncwarp();

    // mean[i][lane] = sum_c Z[i][c] * Z[lane][c]
    float rr[N];
#pragma unroll
    for (int c = 0; c < N; ++c) rr[c] = sB[lane * LDT + c];

    float* o = out + (size_t)site * (N * N);
    for (int i = 0; i < N; ++i) {
        float acc = 0.0f;
#pragma unroll
        for (int c = 0; c < N; ++c)
            acc = fmaf(sB[i * LDT + c], rr[c], acc);  // broadcast reads
        o[i * N + lane] = acc;                        // coalesced
    }
}

extern "C" void kernel_launch(void* const* d_in, const int* in_sizes, int n_in,
                              void* d_out, int out_size)
{
    const float* x  = (const float*)d_in[0];
    const float* rw = (const float*)d_in[1];
    float* out = (float*)d_out;

    const int K     = in_sizes[1];               // KERNEL_SIZE (= 2 for this problem)
    const int t_out = T_DIM - K + 1;             // 127
    const int sites = B_DIM * t_out * NB_BANDS;  // 9144
    const int nblocks = (sites + WARPS_PER_CTA - 1) / WARPS_PER_CTA;  // 2286

    wfm_kernel<<<nblocks, NTHREADS>>>(x, rw, out, t_out);
}

// round 9
// speedup vs baseline: 1.0290x; 1.0290x over previous
#include <cuda_runtime.h>
#include <math.h>

#define N 32
#define LDT 33                 // padded tile leading dim
#define WARPS_PER_CTA 4
#define NTHREADS (WARPS_PER_CTA * 32)
#define NSWEEP 6
#define MINSWEEP 3
#define JTOL2 1e-6f            // squared scale-free residual tolerance (1e-3^2)
#define EPS 1e-6f
#define NB_BANDS 9
#define T_DIM 128
#define B_DIM 8

typedef unsigned long long ull;

// ---- packed 2xfp32 helpers (Blackwell FFMA2 path, PTX-only) ----
__device__ __forceinline__ ull pack2(float x, float y)
{ ull r; asm("mov.b64 %0, {%1, %2};" : "=l"(r) : "f"(x), "f"(y)); return r; }
__device__ __forceinline__ void unpack2(ull v, float& x, float& y)
{ asm("mov.b64 {%0, %1}, %2;" : "=f"(x), "=f"(y) : "l"(v)); }
__device__ __forceinline__ ull mul2(ull a, ull b)
{ ull d; asm("mul.rn.f32x2 %0, %1, %2;" : "=l"(d) : "l"(a), "l"(b)); return d; }
__device__ __forceinline__ ull fma2(ull a, ull b, ull c)
{ ull d; asm("fma.rn.f32x2 %0, %1, %2, %3;" : "=l"(d) : "l"(a), "l"(b), "l"(c)); return d; }

// Jacobi rotation for implicit 2x2 [[np, bpq],[bpq, nq]]. MUFU-fast, clamped.
__device__ __forceinline__ void fastrot(float np, float nq, float bpq,
                                        float& c, float& s)
{
    if (fabsf(bpq) > 1e-20f) {
        float tau = __fdividef(nq - np, 2.0f * bpq);
        tau = fminf(fmaxf(tau, -1e15f), 1e15f);
        float t2  = fmaf(tau, tau, 1.0f);
        float den = fabsf(tau) + t2 * rsqrtf(t2);      // |tau| + sqrt(1+tau^2)
        float tt  = __fdividef(1.0f, den);
        tt = (tau >= 0.0f) ? tt : -tt;
        c = rsqrtf(fmaf(tt, tt, 1.0f));
        s = tt * c;
    } else { c = 1.0f; s = 0.0f; }
}

// Warp-cooperative in-place Cholesky (lower) of SPD 32x32 in smem. lane = row.
__device__ __forceinline__ void warp_chol(float* S, int lane)
{
    for (int k = 0; k < N; ++k) {
        float akk = S[k * LDT + k];
        float inv = rsqrtf(fmaxf(akk, 1e-12f));
        __syncwarp();
        float lik = 0.0f;
        if (lane >= k) {
            float v = S[lane * LDT + k];
            lik = (lane == k) ? akk * inv : v * inv;
            S[lane * LDT + k] = lik;
        }
        __syncwarp();
        if (lane > k) {
            for (int j = k + 1; j <= lane; ++j)
                S[lane * LDT + j] -= lik * S[j * LDT + k];
        }
        __syncwarp();
    }
}

// ---------------------------------------------------------------------------
// One WARP per output site:
//   L = chol(A); Lb = chol(B); G = L^{-1} Lb  (lane = column, registers)
//   one-sided Jacobi on G's columns (XOR ordering, packed f32x2 math)
//   mean = Z Z^T with z_c = L g_c * lambda_c^{(w2-1)/2}
// Requires K == 2.
// ---------------------------------------------------------------------------
__global__ void __launch_bounds__(NTHREADS, 6)
wfm_kernel(const float* __restrict__ x, const float* __restrict__ rw,
           float* __restrict__ out, int t_out)
{
    __shared__ float tiles[WARPS_PER_CTA][2][N * LDT];

    const int lane = threadIdx.x & 31;
    const int wrp  = threadIdx.x >> 5;
    float* sA = tiles[wrp][0];                 // A -> L  (upper zeroed later)
    float* sB = tiles[wrp][1];                 // B -> Lb -> Z

    const int site = blockIdx.x * WARPS_PER_CTA + wrp;
    const int band = site % NB_BANDS;
    const int tmp  = site / NB_BANDS;
    const int tt   = tmp % t_out;
    const int b    = tmp / t_out;

    const float* Ma = x + ((size_t)(b * T_DIM + tt) * NB_BANDS + band) * (size_t)(N * N);
    const float* Mb = Ma + (size_t)NB_BANDS * N * N;

    // softmax weight w2 (K == 2)
    float r0 = rw[0], r1 = rw[1];
    float mx = fmaxf(r0, r1);
    float e0 = __expf(r0 - mx), e1 = __expf(r1 - mx);
    const float w2 = e1 / (e0 + e1);

    // load A, B into per-warp tiles (coalesced)
#pragma unroll
    for (int t = 0; t < N; ++t) {
        sA[t * LDT + lane] = Ma[t * N + lane];
        sB[t * LDT + lane] = Mb[t * N + lane];
    }
    __syncwarp();

    warp_chol(sA, lane);                       // sA lower = L
    warp_chol(sB, lane);                       // sB lower = Lb

    // zero strict upper of sA (so Z = L*u can be unconditional later)
#pragma unroll
    for (int j = 0; j < N; ++j)
        if (j > lane) sA[lane * LDT + j] = 0.0f;
    __syncwarp();

    // G = L^{-1} Lb, lane = column c. Lower triangular: u[k] = 0 for k < c.
    float uu[N];
#pragma unroll
    for (int k = 0; k < N; ++k) {
        float acc = sB[k * LDT + lane];
#pragma unroll
        for (int j = 0; j < k; ++j)
            acc -= sA[k * LDT + j] * uu[j];    // broadcast reads of L row k
        float val = acc * __fdividef(1.0f, sA[k * LDT + k]);
        uu[k] = (k >= lane) ? val : 0.0f;
    }

    // pack column into 16 x f32x2
    ull u2[N / 2];
#pragma unroll
    for (int i = 0; i < N / 2; ++i) u2[i] = pack2(uu[2 * i], uu[2 * i + 1]);

    float nu;                                  // ||u||^2, maintained exactly
    {
        ull acc = 0ull;
#pragma unroll
        for (int i = 0; i < N / 2; ++i) acc = fma2(u2[i], u2[i], acc);
        float ax, ay; unpack2(acc, ax, ay);
        nu = ax + ay;
    }

    // ---------------- one-sided Jacobi, XOR ordering, packed math ----------
#pragma unroll 1
    for (int sweep = 0; sweep < NSWEEP; ++sweep) {
        bool bad = false;
#pragma unroll 1
        for (int m = 1; m < 32; ++m) {
            const int partner = lane ^ m;

            ull pu2[N / 2];
#pragma unroll
            for (int i = 0; i < N / 2; ++i)
                pu2[i] = __shfl_xor_sync(0xffffffffu, u2[i], m);

            // pair dot (identical products + order in both lanes of a pair)
            ull dacc = 0ull;
#pragma unroll
            for (int i = 0; i < N / 2; ++i) dacc = fma2(u2[i], pu2[i], dacc);
            float dx, dy; unpack2(dacc, dx, dy);
            float bu = dx + dy;

            float pn  = __shfl_xor_sync(0xffffffffu, nu, m);
            bool  isp = lane < partner;

            bad |= (bu * bu > nu * pn * JTOL2);

            float np = isp ? nu : pn;
            float nq = isp ? pn : nu;

            float c, s;
            fastrot(np, nq, bu, c, s);
            float ss = isp ? -s : s;

            ull c2  = pack2(c, c);
            ull ss2 = pack2(ss, ss);
#pragma unroll
            for (int i = 0; i < N / 2; ++i)
                u2[i] = fma2(ss2, pu2[i], mul2(c2, u2[i]));

            // exact norm rotation identity
            nu = c * c * nu + s * s * pn + 2.0f * ss * c * bu;
        }
        if (sweep >= MINSWEEP - 1 && !__any_sync(0xffffffffu, bad)) break;
    }

    // eigenvalue = exact final column norm; scale: z = L u * lam^{(w2-1)/2}
    float lam;
    {
        ull acc = 0ull;
#pragma unroll
        for (int i = 0; i < N / 2; ++i) acc = fma2(u2[i], u2[i], acc);
        float ax, ay; unpack2(acc, ax, ay);
        lam = fmaxf(ax + ay, EPS);
    }
    float scale = __expf(0.5f * (w2 - 1.0f) * __logf(lam));
    {
        ull sc2 = pack2(scale, scale);
#pragma unroll
        for (int i = 0; i < N / 2; ++i) u2[i] = mul2(sc2, u2[i]);
    }

    // unpack for the smem products
#pragma unroll
    for (int i = 0; i < N / 2; ++i) unpack2(u2[i], uu[2 * i], uu[2 * i + 1]);

    __syncwarp();
    // Z = L * u (store columns into sB, reuse tile)
    for (int i = 0; i < N; ++i) {
        float acc = 0.0f;
#pragma unroll
        for (int j = 0; j < N; ++j)
            acc = fmaf(sA[i * LDT + j], uu[j], acc);  // upper of L is zeroed
        sB[i * LDT + lane] = acc;
    }
    __syncwarp();

    // mean[i][lane] = sum_c Z[i][c] * Z[lane][c]
    float rr[N];
#pragma unroll
    for (int c = 0; c < N; ++c) rr[c] = sB[lane * LDT + c];

    float* o = out + (size_t)site * (N * N);
    for (int i = 0; i < N; ++i) {
        float acc = 0.0f;
#pragma unroll
        for (int c = 0; c < N; ++c)
            acc = fmaf(sB[i * LDT + c], rr[c], acc);  // broadcast reads
        o[i * N + lane] = acc;                        // coalesced
    }
}

extern "C" void kernel_launch(void* const* d_in, const int* in_sizes, int n_in,
                              void* d_out, int out_size)
{
    const float* x  = (const float*)d_in[0];
    const float* rw = (const float*)d_in[1];
    float* out = (float*)d_out;

    const int K     = in_sizes[1];               // KERNEL_SIZE (= 2 for this problem)
    const int t_out = T_DIM - K + 1;             // 127
    const int sites = B_DIM * t_out * NB_BANDS;  // 9144
    const int nblocks = (sites + WARPS_PER_CTA - 1) / WARPS_PER_CTA;  // 2286

    wfm_kernel<<<nblocks, NTHREADS>>>(x, rw, out, t_out);
}